// round 9
// baseline (speedup 1.0000x reference)
#include <cuda_runtime.h>
#include <cuda_bf16.h>
#include <cstdint>

// Problem: B=4, L=2048, H=8, D=64.
// Reference math collapses: out[b,q,h,d] = (sum_w softmax[.]) * (sum_e V[b,e,h,d])
//                                        = 1 * sum_l V[b,l,h,d]
// Q, K are dead inputs. Column-sum V over L, broadcast over q.
// This round: bulk-async (UBLKCP) streaming for both the V read (stage 1)
// and the output write (stage 3) — sidesteps ptxas's serialized-LDG register
// allocation that pinned us at ~2.5 TB/s.

#define B_DIM 4
#define L_DIM 2048
#define HD4 128            // H*D/4 = 128 float4 per (b,l) row
#define S1_CHUNKS 256      // per batch; 8 rows (16 KB) per chunk
#define S1_ROWS 8
#define S2_GROUPS 8        // per batch; each reduces 32 chunks
#define S2_SPAN 32
#define Q_PER_BLOCK 8      // stage-3 tile = 8 q rows = 16 KB
#define TILE_BYTES (S1_ROWS * HD4 * 16)   // 16384

// Scratch (allocation-free __device__ globals)
__device__ float4 g_partial[B_DIM * S1_CHUNKS * HD4];   // 2 MB (L2-resident)
__device__ float4 g_mid[B_DIM * S2_GROUPS * HD4];       // 16 KB

__device__ __forceinline__ float4 f4add(float4 a, float4 b) {
    a.x += b.x; a.y += b.y; a.z += b.z; a.w += b.w; return a;
}

__device__ __forceinline__ uint32_t smem_u32(const void* p) {
    return (uint32_t)__cvta_generic_to_shared(p);
}

__device__ __forceinline__ void mbar_init(uint32_t a, uint32_t count) {
    asm volatile("mbarrier.init.shared.b64 [%0], %1;" :: "r"(a), "r"(count) : "memory");
}
__device__ __forceinline__ void mbar_expect_tx(uint32_t a, uint32_t bytes) {
    asm volatile("mbarrier.arrive.expect_tx.shared.b64 _, [%0], %1;"
                 :: "r"(a), "r"(bytes) : "memory");
}
__device__ __forceinline__ void mbar_wait_parity0(uint32_t a) {
    uint32_t done;
    asm volatile(
        "{\n\t.reg .pred p;\n\t"
        "mbarrier.try_wait.parity.shared.b64 p, [%1], 0;\n\t"
        "selp.b32 %0, 1, 0, p;\n\t}"
        : "=r"(done) : "r"(a) : "memory");
    while (!done) {
        asm volatile(
            "{\n\t.reg .pred p;\n\t"
            "mbarrier.try_wait.parity.shared.b64 p, [%1], 0;\n\t"
            "selp.b32 %0, 1, 0, p;\n\t}"
            : "=r"(done) : "r"(a) : "memory");
    }
}

// Stage 1: 1024 blocks x 128 threads. One UBLKCP of 16 KB (8 V rows) into
// smem, then a conflict-free smem reduction to one 2 KB partial row.
__global__ void __launch_bounds__(HD4) vpartial_kernel(const float* __restrict__ V) {
    __shared__ alignas(128) float4 tile[S1_ROWS * HD4];   // 16 KB
    __shared__ alignas(8) uint64_t mbar;

    const int blk = blockIdx.x;
    const int b = blk >> 8;
    const int chunk = blk & 255;
    const int t = threadIdx.x;
    const uint32_t mb = smem_u32(&mbar);
    const uint32_t st = smem_u32(tile);

    if (t == 0) mbar_init(mb, 1);
    __syncthreads();
    if (t == 0) {
        mbar_expect_tx(mb, TILE_BYTES);
        const float* src = V + ((size_t)(b * L_DIM + chunk * S1_ROWS)) * (HD4 * 4);
        asm volatile(
            "cp.async.bulk.shared::cluster.global.mbarrier::complete_tx::bytes "
            "[%0], [%1], %2, [%3];"
            :: "r"(st), "l"(src), "r"((uint32_t)TILE_BYTES), "r"(mb) : "memory");
    }
    mbar_wait_parity0(mb);

    // Reduce 8 rows: thread t owns float4-column t. LDS.128, conflict-free.
    float4 a0 = f4add(tile[0 * HD4 + t], tile[1 * HD4 + t]);
    float4 a1 = f4add(tile[2 * HD4 + t], tile[3 * HD4 + t]);
    float4 a2 = f4add(tile[4 * HD4 + t], tile[5 * HD4 + t]);
    float4 a3 = f4add(tile[6 * HD4 + t], tile[7 * HD4 + t]);
    g_partial[(b * S1_CHUNKS + chunk) * HD4 + t] = f4add(f4add(a0, a1), f4add(a2, a3));
}

// Stage 2: 32 blocks x 128 threads; block (b,g) reduces chunks [g*32, g*32+32)
// from L2-resident g_partial (2 MB).
__global__ void __launch_bounds__(HD4) vmid_kernel() {
    const int b = blockIdx.x >> 3;
    const int g = blockIdx.x & 7;
    const int t = threadIdx.x;
    const float4* src = g_partial + (b * S1_CHUNKS + g * S2_SPAN) * HD4 + t;
    float4 a0 = make_float4(0.f, 0.f, 0.f, 0.f), a1 = a0, a2 = a0, a3 = a0;
#pragma unroll
    for (int k = 0; k < S2_SPAN; k += 4) {
        a0 = f4add(a0, src[(k + 0) * HD4]);
        a1 = f4add(a1, src[(k + 1) * HD4]);
        a2 = f4add(a2, src[(k + 2) * HD4]);
        a3 = f4add(a3, src[(k + 3) * HD4]);
    }
    g_mid[(b * S2_GROUPS + g) * HD4 + t] = f4add(f4add(a0, a1), f4add(a2, a3));
}

// Stage 3: 1024 blocks x 128 threads. Thread t finishes the 8-way mid
// reduction (16 KB L2-hot), replicates its float4 into 8 q-rows of a 16 KB
// smem tile, and one thread bulk-stores the tile to GMEM.
__global__ void __launch_bounds__(HD4) bcast_kernel(float* __restrict__ out) {
    __shared__ alignas(128) float4 tile[Q_PER_BLOCK * HD4];   // 16 KB

    const int blk = blockIdx.x;
    const int b = blk >> 8;                      // 256 blocks per batch
    const int q0 = (blk & 255) * Q_PER_BLOCK;
    const int t = threadIdx.x;

    const float4* m = g_mid + b * S2_GROUPS * HD4 + t;
    float4 v = f4add(f4add(f4add(__ldg(m + 0 * HD4), __ldg(m + 1 * HD4)),
                           f4add(__ldg(m + 2 * HD4), __ldg(m + 3 * HD4))),
                     f4add(f4add(__ldg(m + 4 * HD4), __ldg(m + 5 * HD4)),
                           f4add(__ldg(m + 6 * HD4), __ldg(m + 7 * HD4))));
#pragma unroll
    for (int i = 0; i < Q_PER_BLOCK; ++i)
        tile[i * HD4 + t] = v;                   // STS.128, conflict-free
    __syncthreads();

    if (t == 0) {
        asm volatile("fence.proxy.async;" ::: "memory");
        float* dst = out + ((size_t)(b * L_DIM + q0)) * (HD4 * 4);
        asm volatile(
            "cp.async.bulk.global.shared::cta.bulk_group [%0], [%1], %2;"
            :: "l"(dst), "r"(smem_u32(tile)), "r"((uint32_t)TILE_BYTES) : "memory");
        asm volatile("cp.async.bulk.commit_group;" ::: "memory");
        asm volatile("cp.async.bulk.wait_group 0;" ::: "memory");
    }
}

extern "C" void kernel_launch(void* const* d_in, const int* in_sizes, int n_in,
                              void* d_out, int out_size) {
    // inputs: [0] queries, [1] keys, [2] values (float32). Q, K unused by the math.
    const float* V = (const float*)d_in[2];
    float* out = (float*)d_out;

    vpartial_kernel<<<B_DIM * S1_CHUNKS, HD4>>>(V);
    vmid_kernel<<<B_DIM * S2_GROUPS, HD4>>>();
    bcast_kernel<<<B_DIM * (L_DIM / Q_PER_BLOCK), HD4>>>(out);
}